// round 7
// baseline (speedup 1.0000x reference)
#include <cuda_runtime.h>
#include <cstdint>

// out[p] = (L >= 0) || (missing(p) - L >= 0.5), float 0.0/1.0
// L = 7-point Laplacian (6*center - face neighbors, zero padding);
// missing(p) = # out-of-grid face neighbors (kernel sums to 0 =>
// conv(1-m,k) = missing(p) - conv(m,k)).
//
// cp.async smem pipeline: block owns a 192x * 8y tile and marches 24 z
// planes. 8-slot ring of (10-row x 192) input planes + one zero plane.
// Depth-5 plane prefetch in flight; compute reads smem only.

#define DSZ 192
#define TY 8
#define ROWS (TY + 2)                 // 10 (y-halo)
#define PLANE_F (ROWS * DSZ)          // 1920 floats
#define PLANE_B (PLANE_F * 4)         // 7680 bytes
#define NSLOT 8
#define ZSLAB 24
#define NTHREADS 384
#define SMEM_BYTES ((NSLOT + 1) * PLANE_B)   // 69120

__device__ __forceinline__ void cp_async16(uint32_t dst, const void* src) {
    asm volatile("cp.async.cg.shared.global [%0], [%1], 16;\n" :: "r"(dst), "l"(src));
}
__device__ __forceinline__ void cp_commit() {
    asm volatile("cp.async.commit_group;\n" ::: "memory");
}
__device__ __forceinline__ void cp_wait2() {
    asm volatile("cp.async.wait_group 2;\n" ::: "memory");
}

__global__ __launch_bounds__(NTHREADS) void mask_kernel(
    const float* __restrict__ m, float* __restrict__ out)
{
    extern __shared__ float smem[];

    const int tid = threadIdx.x;
    const int q = tid % 48;            // x quad
    const int r = tid / 48;            // y row within tile (0..7)
    const int y0 = blockIdx.x * TY;    // 24 y-tiles
    const int bz = blockIdx.y;         // slab(8) * batch(2)
    const int slab = bz & 7;
    const int b = bz >> 3;
    const int z0 = slab * ZSLAB;

    const size_t plane = (size_t)DSZ * DSZ;
    const float* mb = m + (size_t)b * DSZ * plane;
    const uint32_t smem_u32 = (uint32_t)__cvta_generic_to_shared(smem);

    // zero everything once: y-halo rows that are never cp.async-written stay 0,
    // and slot NSLOT is the permanent zero plane (for z = -1 / 192).
    for (int i = tid; i < (NSLOT + 1) * PLANE_F / 4; i += NTHREADS)
        ((float4*)smem)[i] = make_float4(0.f, 0.f, 0.f, 0.f);
    __syncthreads();

    auto issue_plane = [&](int zg) {
        if (zg >= 0 && zg < DSZ) {
            const uint32_t dst0 = smem_u32 + (uint32_t)(zg & 7) * PLANE_B;
            const float* src0 = mb + (size_t)zg * plane;
            #pragma unroll
            for (int idx = tid; idx < ROWS * 48; idx += NTHREADS) {
                const int row = idx / 48;
                const int qq = idx % 48;
                const int y = y0 - 1 + row;
                if (y >= 0 && y < DSZ)
                    cp_async16(dst0 + (uint32_t)(row * DSZ + qq * 4) * 4,
                               src0 + (size_t)y * DSZ + qq * 4);
            }
        }
        cp_commit();   // empty group if skipped: keeps wait accounting uniform
    };

    // prologue: planes z0-1 .. z0+3 (5 groups)
    #pragma unroll
    for (int k = -1; k <= 3; ++k) issue_plane(z0 + k);

    const int x0 = q * 4;
    const int y = y0 + r;
    const int off = (r + 1) * DSZ + x0;
    const float missY = (float)((int)(y == 0) + (int)(y == DSZ - 1));
    const float eL = (float)(int)(x0 == 0);
    const float eR = (float)(int)(x0 + 4 == DSZ);
    float* qp = out + (((size_t)b * DSZ + z0) * DSZ + y) * DSZ + x0;

    for (int z = z0; z < z0 + ZSLAB; ++z) {
        cp_wait2();          // newest 2 groups (z+3, z+2) may be pending; z+1 done
        __syncthreads();     // everyone's copies visible; prior compute drained

        const float* pa = (z > 0)       ? smem + (size_t)((z - 1) & 7) * PLANE_F
                                        : smem + (size_t)NSLOT * PLANE_F;
        const float* pb = smem + (size_t)(z & 7) * PLANE_F;
        const float* pc = (z < DSZ - 1) ? smem + (size_t)((z + 1) & 7) * PLANE_F
                                        : smem + (size_t)NSLOT * PLANE_F;

        float4 c  = *(const float4*)(pb + off);
        float4 ym = *(const float4*)(pb + off - DSZ);
        float4 yp = *(const float4*)(pb + off + DSZ);
        float4 zm = *(const float4*)(pa + off);
        float4 zp = *(const float4*)(pc + off);
        float  xl = (x0 > 0)       ? pb[off - 1] : 0.f;
        float  xr = (x0 + 4 < DSZ) ? pb[off + 4] : 0.f;

        float L0 = 6.f * c.x - (xl  + c.y + ym.x + yp.x + zm.x + zp.x);
        float L1 = 6.f * c.y - (c.x + c.z + ym.y + yp.y + zm.y + zp.y);
        float L2 = 6.f * c.z - (c.y + c.w + ym.z + yp.z + zm.z + zp.z);
        float L3 = 6.f * c.w - (c.z + xr  + ym.w + yp.w + zm.w + zp.w);

        const float mz = missY + (float)((int)(z == 0) + (int)(z == DSZ - 1));
        const float f0 = mz + eL;
        const float f3 = mz + eR;

        float4 o;
        o.x = ((L0 >= 0.f) || (f0 - L0 >= 0.5f)) ? 1.f : 0.f;
        o.y = ((L1 >= 0.f) || (mz - L1 >= 0.5f)) ? 1.f : 0.f;
        o.z = ((L2 >= 0.f) || (mz - L2 >= 0.5f)) ? 1.f : 0.f;
        o.w = ((L3 >= 0.f) || (f3 - L3 >= 0.5f)) ? 1.f : 0.f;
        __stcs((float4*)qp, o);
        qp += plane;

        // prefetch plane z+4 (overwrites slot of z-4, last read at compute z-3,
        // fenced by the per-iteration __syncthreads above)
        const int zg = z + 4;
        if (zg <= z0 + ZSLAB) issue_plane(zg); else cp_commit();
    }
}

extern "C" void kernel_launch(void* const* d_in, const int* in_sizes, int n_in,
                              void* d_out, int out_size)
{
    const float* m = (const float*)d_in[0];
    float* out = (float*)d_out;

    static int configured = 0;
    if (!configured) {
        cudaFuncSetAttribute(mask_kernel,
                             cudaFuncAttributeMaxDynamicSharedMemorySize,
                             SMEM_BYTES);
        configured = 1;
    }

    dim3 block(NTHREADS, 1, 1);
    dim3 grid(DSZ / TY, 2 * (DSZ / ZSLAB), 1);   // 24 y-tiles x 16 (batch*slab)
    mask_kernel<<<grid, block, SMEM_BYTES>>>(m, out);
}

// round 8
// speedup vs baseline: 1.4747x; 1.4747x over previous
#include <cuda_runtime.h>
#include <cstdint>

// out[p] = (L >= 0) || (missing(p) - L >= 0.5), written as float 0.0/1.0
// L = 7-point Laplacian (6*center - face neighbors, zero padding);
// missing(p) = count of out-of-grid face neighbors (kernel sums to 0, so
// conv(1-m,k) = missing(p) - conv(m,k)).
//
// R4 (best: rolling-z x-quad, KZ=6, 5 CTAs/SM) + __stcs streaming stores:
// output is write-once, keep it evict-first in L2 so the input stays
// L2-resident across the whole launch.

#define DSZ 192
#define KZ  6
#define ZT  (DSZ / KZ)   // 32 z-tiles

__global__ __launch_bounds__(384, 5) void mask_kernel(
    const float* __restrict__ m, float* __restrict__ out)
{
    const int tx = threadIdx.x;                       // 0..47 -> x quad
    const int y  = blockIdx.y * blockDim.y + threadIdx.y;
    const int zb = blockIdx.z;
    const int z0 = (zb & (ZT - 1)) * KZ;
    const int b  = zb / ZT;
    const int x0 = tx * 4;

    const size_t plane = (size_t)DSZ * DSZ;
    const float* p = m + (((size_t)b * DSZ + z0) * DSZ + y) * DSZ + x0;
    float* q = out + (((size_t)b * DSZ + z0) * DSZ + y) * DSZ + x0;

    const float4 zero4 = make_float4(0.f, 0.f, 0.f, 0.f);
    const bool hasYm = (y > 0);
    const bool hasYp = (y < DSZ - 1);
    const bool hasXl = (x0 > 0);
    const bool hasXr = (x0 + 4 < DSZ);
    const int  missY = (int)(!hasYm) + (int)(!hasYp);
    const float missE0 = (float)(missY + (int)(!hasXl));
    const float missE3 = (float)(missY + (int)(!hasXr));
    const float missM  = (float)missY;

    float4 A = (z0 > 0) ? *(const float4*)(p - plane) : zero4;  // z-1
    float4 B = *(const float4*)(p);                              // z

    #pragma unroll
    for (int iz = 0; iz < KZ; ++iz) {
        const int z = z0 + iz;
        float4 C = (z < DSZ - 1) ? *(const float4*)(p + plane) : zero4;  // z+1
        float4 ym = hasYm ? *(const float4*)(p - DSZ) : zero4;
        float4 yp = hasYp ? *(const float4*)(p + DSZ) : zero4;
        float  xl = hasXl ? __ldg(p - 1) : 0.f;
        float  xr = hasXr ? __ldg(p + 4) : 0.f;

        float L0 = 6.f * B.x - (xl  + B.y + ym.x + yp.x + A.x + C.x);
        float L1 = 6.f * B.y - (B.x + B.z + ym.y + yp.y + A.y + C.y);
        float L2 = 6.f * B.z - (B.y + B.w + ym.z + yp.z + A.z + C.z);
        float L3 = 6.f * B.w - (B.z + xr  + ym.w + yp.w + A.w + C.w);

        const float mz = (float)((int)(z == 0) + (int)(z == DSZ - 1));
        const float f0 = missE0 + mz;
        const float fm = missM  + mz;
        const float f3 = missE3 + mz;

        float4 o;
        o.x = ((L0 >= 0.f) || (f0 - L0 >= 0.5f)) ? 1.f : 0.f;
        o.y = ((L1 >= 0.f) || (fm - L1 >= 0.5f)) ? 1.f : 0.f;
        o.z = ((L2 >= 0.f) || (fm - L2 >= 0.5f)) ? 1.f : 0.f;
        o.w = ((L3 >= 0.f) || (f3 - L3 >= 0.5f)) ? 1.f : 0.f;

        __stcs((float4*)q, o);

        A = B; B = C;
        p += plane; q += plane;
    }
}

extern "C" void kernel_launch(void* const* d_in, const int* in_sizes, int n_in,
                              void* d_out, int out_size)
{
    const float* m = (const float*)d_in[0];
    float* out = (float*)d_out;

    dim3 block(48, 8, 1);                 // 384 threads: full row x 8 rows
    dim3 grid(1, DSZ / 8, 2 * ZT);        // y-tiles, (batch * z-tiles)
    mask_kernel<<<grid, block>>>(m, out);
}